// round 10
// baseline (speedup 1.0000x reference)
#include <cuda_runtime.h>
#include <cuda_bf16.h>
#include <math.h>
#include <stdint.h>

#define B_   256
#define N_   300
#define T_   64
#define FIN  3
#define U_   256
#define G_   1024            // 4*U_
#define K0   900             // N_*FIN
#define K0P  960             // padded to multiple of 64
#define M_   16384           // B_*T_
#define FOUT 2
#define ND   600             // N_*FOUT

// ---------------- scratch (static device globals; no allocation) ----------------
__device__ __nv_bfloat16 g_ahi[(size_t)M_ * K0P];   // x transposed, bf16-hi
__device__ __nv_bfloat16 g_alo[(size_t)M_ * K0P];   // x transposed, bf16-lo
__device__ __nv_bfloat16 g_bhi[(size_t)G_ * K0P];   // weight K-major, bf16-hi (max size)
__device__ __nv_bfloat16 g_blo[(size_t)G_ * K0P];
__device__ __nv_bfloat16 g_uhi[(size_t)G_ * U_];    // recurrent U, permuted K-major, hi
__device__ __nv_bfloat16 g_ulo[(size_t)G_ * U_];
__device__ __nv_bfloat16 g_hhi[(size_t)M_ * U_];    // h sequence bf16-hi
__device__ __nv_bfloat16 g_hlo[(size_t)M_ * U_];    // h sequence bf16-lo
__device__ float    g_zx[(size_t)M_ * G_];          // gate pre-acts

// single dynamic-smem symbol for all kernels
extern __shared__ char dynsmem[];

// ---------------- bf16 2-term split ----------------
__device__ __forceinline__ void bf16split(float v, __nv_bfloat16& hi, __nv_bfloat16& lo) {
    hi = __float2bfloat16(v);
    lo = __float2bfloat16(v - __bfloat162float(hi));
}

// ---------------- coalesced input transpose + split ----------------
// x (B,N,T,F) -> (B*T, 960) bf16 hi/lo, via smem tile (32 n-rows x 192 floats).
__global__ void transpose_x_kernel(const float* __restrict__ x) {
    __shared__ float tile[32][195];          // pitch 195 to spread banks
    const int tid = threadIdx.x;
    const int b = blockIdx.y;
    const int n0 = blockIdx.x * 32;
    const float* xb = x + (size_t)b * N_ * T_ * FIN + (size_t)n0 * T_ * FIN;

    // coalesced read: each n-row is 192 contiguous floats
    for (int idx = tid; idx < 32 * 192; idx += 256) {
        int nl = idx / 192, j = idx - nl * 192;
        float v = (n0 + nl < N_) ? xb[nl * 192 + j] : 0.f;
        tile[nl][j] = v;
    }
    __syncthreads();

    // coalesced write: per output row t, 96 contiguous cols (bf16)
    long rowbase = (long)b * T_;
    for (int idx = tid; idx < 64 * 96; idx += 256) {
        int t = idx / 96, cl = idx - t * 96;
        int nl = cl / 3, f = cl - nl * 3;
        float v = tile[nl][t * 3 + f];
        __nv_bfloat16 hi, lo;
        bf16split(v, hi, lo);
        long o = (rowbase + t) * K0P + n0 * 3 + cl;
        g_ahi[o] = hi;
        g_alo[o] = lo;
    }
}

// ---------------- weight transpose + split: W (K,N) -> (N, Ks) K-major hi/lo ----------------
__global__ void wtrans_kernel(const float* __restrict__ W, int K, int N, int Ks) {
    long i = (long)blockIdx.x * blockDim.x + threadIdx.x;
    if (i >= (long)N * Ks) return;
    int k = (int)(i % Ks);
    int n = (int)(i / Ks);
    float v = (k < K) ? W[(long)k * N + n] : 0.f;
    __nv_bfloat16 hi, lo;
    bf16split(v, hi, lo);
    g_bhi[i] = hi;
    g_blo[i] = lo;
}

// ---------------- recurrent-U permute + split ----------------
// permuted col cp -> (gate, unit): ublk=cp>>7, local=cp&127, warp_n=local>>4, c=local&15,
// gate=(c>>3)*2+(c&1), unit=ublk*32+warp_n*4+((c>>1)&3); orig col = gate*256+unit.
__global__ void utrans_kernel(const float* __restrict__ U) {
    long i = (long)blockIdx.x * blockDim.x + threadIdx.x;
    if (i >= (long)G_ * U_) return;
    int k  = (int)(i & 255);
    int cp = (int)(i >> 8);
    int ublk = cp >> 7;
    int local = cp & 127;
    int warp_n = local >> 4;
    int c = local & 15;
    int gate = ((c >> 3) << 1) | (c & 1);
    int unit = ublk * 32 + warp_n * 4 + ((c >> 1) & 3);
    float v = U[(long)k * G_ + gate * U_ + unit];
    __nv_bfloat16 hi, lo;
    bf16split(v, hi, lo);
    g_uhi[i] = hi;
    g_ulo[i] = lo;
}

// ================= mma.sync / cluster helpers =================
__device__ __forceinline__ uint32_t smem_u32(const void* p) {
    uint32_t a;
    asm("{ .reg .u64 t; cvta.to.shared.u64 t, %1; cvt.u32.u64 %0, t; }" : "=r"(a) : "l"(p));
    return a;
}
__device__ __forceinline__ uint32_t sw128(uint32_t o) { return o ^ ((o >> 3) & 0x70); }

__device__ __forceinline__ void ldsm_x4(uint32_t addr, uint32_t& r0, uint32_t& r1,
                                        uint32_t& r2, uint32_t& r3) {
    asm volatile("ldmatrix.sync.aligned.m8n8.x4.shared.b16 {%0,%1,%2,%3}, [%4];"
                 : "=r"(r0), "=r"(r1), "=r"(r2), "=r"(r3) : "r"(addr));
}

__device__ __forceinline__ void mma_bf16(float* d, const uint32_t* a, uint32_t b0, uint32_t b1) {
    asm volatile(
        "mma.sync.aligned.m16n8k16.row.col.f32.bf16.bf16.f32 "
        "{%0,%1,%2,%3}, {%4,%5,%6,%7}, {%8,%9}, {%0,%1,%2,%3};"
        : "+f"(d[0]), "+f"(d[1]), "+f"(d[2]), "+f"(d[3])
        : "r"(a[0]), "r"(a[1]), "r"(a[2]), "r"(a[3]), "r"(b0), "r"(b1));
}

__device__ __forceinline__ void cp_async16(uint32_t dst, const void* src, uint32_t src_bytes) {
    asm volatile("cp.async.cg.shared.global [%0], [%1], 16, %2;"
                 :: "r"(dst), "l"(src), "r"(src_bytes));
}

__device__ __forceinline__ uint32_t mapa_cluster(uint32_t addr, uint32_t rank) {
    uint32_t r;
    asm("mapa.shared::cluster.u32 %0, %1, %2;" : "=r"(r) : "r"(addr), "r"(rank));
    return r;
}
__device__ __forceinline__ void ld_dsmem4(uint32_t addr, uint32_t& a, uint32_t& b,
                                          uint32_t& c, uint32_t& d) {
    asm volatile("ld.shared::cluster.v4.b32 {%0,%1,%2,%3}, [%4];"
                 : "=r"(a), "=r"(b), "=r"(c), "=r"(d) : "r"(addr));
}

// ---------------- tensor-core GEMM (feed-forward): C = A @ B^T + bias ----------------
// 128x128 tile, BK=64, 256 threads, double-buffered cp.async (2 x 64KB stages).
#define ST_A_HI 0
#define ST_A_LO 16384
#define ST_B_HI 32768
#define ST_B_LO 49152
#define STAGE_SZ 65536
#define MM_SMEM  131072

template <bool SCATTER>
__global__ void __launch_bounds__(256, 1)
mma_gemm_kernel(const __nv_bfloat16* __restrict__ Ahi, const __nv_bfloat16* __restrict__ Alo,
                const __nv_bfloat16* __restrict__ Bhi, const __nv_bfloat16* __restrict__ Blo,
                const float* __restrict__ bias, float* __restrict__ C,
                int Ks, int N) {
    char* smem = dynsmem;
    const int tid  = threadIdx.x;
    const int lane = tid & 31;
    const int wid  = tid >> 5;
    const int warp_m = wid >> 2;       // 0..1 -> 64 rows
    const int warp_n = wid & 3;        // 0..3 -> 32 cols
    const int m0 = blockIdx.y * 128;
    const int n0 = blockIdx.x * 128;
    const uint32_t sbase = smem_u32(smem);

    float acc[4][4][4];
#pragma unroll
    for (int i = 0; i < 4; i++)
#pragma unroll
        for (int j = 0; j < 4; j++)
#pragma unroll
            for (int q = 0; q < 4; q++) acc[i][j][q] = 0.f;

    const int iters = Ks >> 6;

    auto load_stage = [&](int kt, int buf) {
        uint32_t bb = sbase + (uint32_t)buf * STAGE_SZ;
#pragma unroll
        for (int i = 0; i < 4; i++) {
            int idx = tid + i * 256;            // 0..1023
            int r = idx >> 3, kq = idx & 7;
            uint32_t so = sw128((uint32_t)(r * 128 + kq * 16));
            cp_async16(bb + ST_A_HI + so, Ahi + (size_t)(m0 + r) * Ks + kt + kq * 8, 16u);
            cp_async16(bb + ST_A_LO + so, Alo + (size_t)(m0 + r) * Ks + kt + kq * 8, 16u);
            uint32_t vbytes = (n0 + r < N) ? 16u : 0u;
            int rcl = (n0 + r < N) ? (n0 + r) : 0;
            cp_async16(bb + ST_B_HI + so, Bhi + (size_t)rcl * Ks + kt + kq * 8, vbytes);
            cp_async16(bb + ST_B_LO + so, Blo + (size_t)rcl * Ks + kt + kq * 8, vbytes);
        }
        asm volatile("cp.async.commit_group;" ::: "memory");
    };

    load_stage(0, 0);

    for (int it = 0; it < iters; it++) {
        if (it + 1 < iters) {
            load_stage((it + 1) << 6, (it + 1) & 1);
            asm volatile("cp.async.wait_group 1;" ::: "memory");
        } else {
            asm volatile("cp.async.wait_group 0;" ::: "memory");
        }
        __syncthreads();

        uint32_t bb = sbase + (uint32_t)(it & 1) * STAGE_SZ;
#pragma unroll
        for (int ks = 0; ks < 4; ks++) {
            const int kb = ks * 16;
            uint32_t bh[2][4], bl[2][4];
#pragma unroll
            for (int ng = 0; ng < 2; ng++) {
                int nrow = warp_n * 32 + ng * 16 + (lane & 7) + (lane >> 4) * 8;
                int koff = kb + ((lane >> 3) & 1) * 8;
                uint32_t so = sw128((uint32_t)(nrow * 128 + koff * 2));
                ldsm_x4(bb + ST_B_HI + so, bh[ng][0], bh[ng][1], bh[ng][2], bh[ng][3]);
                ldsm_x4(bb + ST_B_LO + so, bl[ng][0], bl[ng][1], bl[ng][2], bl[ng][3]);
            }
#pragma unroll
            for (int mf = 0; mf < 4; mf++) {
                int mrow = warp_m * 64 + mf * 16 + (lane & 7) + ((lane >> 3) & 1) * 8;
                int koff = kb + (lane >> 4) * 8;
                uint32_t so = sw128((uint32_t)(mrow * 128 + koff * 2));
                uint32_t ah[4], al[4];
                ldsm_x4(bb + ST_A_HI + so, ah[0], ah[1], ah[2], ah[3]);
                ldsm_x4(bb + ST_A_LO + so, al[0], al[1], al[2], al[3]);
#pragma unroll
                for (int ng = 0; ng < 2; ng++) {
#pragma unroll
                    for (int h = 0; h < 2; h++) {
                        int nf = ng * 2 + h;
                        mma_bf16(acc[mf][nf], ah, bh[ng][h * 2], bh[ng][h * 2 + 1]);
                        mma_bf16(acc[mf][nf], ah, bl[ng][h * 2], bl[ng][h * 2 + 1]);
                        mma_bf16(acc[mf][nf], al, bh[ng][h * 2], bh[ng][h * 2 + 1]);
                    }
                }
            }
        }
        __syncthreads();
    }

    const int g  = lane >> 2;
    const int tq = lane & 3;
#pragma unroll
    for (int mf = 0; mf < 4; mf++) {
#pragma unroll
        for (int nf = 0; nf < 4; nf++) {
            int c = n0 + warp_n * 32 + nf * 8 + tq * 2;
            if (c >= N) continue;
            float bx = bias[c], by = bias[c + 1];
#pragma unroll
            for (int half = 0; half < 2; half++) {
                int m = m0 + warp_m * 64 + mf * 16 + g + half * 8;
                float vx = acc[mf][nf][half * 2 + 0] + bx;
                float vy = acc[mf][nf][half * 2 + 1] + by;
                if (SCATTER) {
                    int b = m >> 6, t = m & 63;
                    int nn = c >> 1;
                    float2* p = (float2*)&C[(((long)b * N_ + nn) * T_ + t) * FOUT];
                    *p = make_float2(vx, vy);
                } else {
                    *(float2*)&C[(size_t)m * N + c] = make_float2(vx, vy);
                }
            }
        }
    }
}

// ---------------- cluster-DSMEM persistent LSTM layer kernel ----------------
// 16 clusters x 8 CTAs. CTA rank = unit-tile (32 units = 128 permuted gate-cols),
// cluster = batch-tile (16 rows). Per step: h slices exchanged through DSMEM
// (local slot write -> barrier.cluster -> pull all 8 slots into ldsm panels).
// Global h stores retained only to feed the downstream GEMMs (off critical path).
#define SM_U_HI  0                    // 4 panels x 16KB
#define SM_U_LO  65536
#define SM_H_HI  131072               // 4 panels x 2KB
#define SM_H_LO  139264
#define SM_SLOT  147456               // 2 bufs x (1KB hi + 1KB lo)
#define LSTM_SMEM 151552

__global__ void __cluster_dims__(8, 1, 1) __launch_bounds__(256, 1)
lstm_kernel(const float* __restrict__ zx,   // (M_,1024) rows b*T+t, cols gate*256+unit
            const __nv_bfloat16* __restrict__ Uphi,  // permuted (1024,256) K-major
            const __nv_bfloat16* __restrict__ Uplo,
            __nv_bfloat16* __restrict__ hhi,         // (M_,256) rows b*T+t
            __nv_bfloat16* __restrict__ hlo) {
    char* smem = dynsmem;
    const uint32_t sbase = smem_u32(smem);
    const int tid  = threadIdx.x;
    const int lane = tid & 31;
    const int warp_n = tid >> 5;            // 0..7, 16 permuted cols each
    const int ublk = blockIdx.x & 7;        // == cluster ctarank
    const int bblk = blockIdx.x >> 3;
    const int b0 = bblk * 16;
    const int cbase = ublk * 128;           // permuted col base

    // ---- load U slice into smem panels (once): 128 rows x 256 k, hi+lo ----
    for (int idx = tid; idx < 4096; idx += 256) {
        int n = idx >> 5, kq = idx & 31;
        int k = kq * 8;
        int p = k >> 6, ko = k & 63;
        uint32_t dst = (uint32_t)(p * 16384) + sw128((uint32_t)(n * 128 + ko * 2));
        *(uint4*)(smem + SM_U_HI + dst) = *(const uint4*)(Uphi + (size_t)(cbase + n) * U_ + k);
        *(uint4*)(smem + SM_U_LO + dst) = *(const uint4*)(Uplo + (size_t)(cbase + n) * U_ + k);
    }
    __syncthreads();

    const int g  = lane >> 2;               // row group 0..7
    const int tq = lane & 3;
    const int ul = warp_n * 4 + tq;          // unit within this block's 32
    const int uglob = ublk * 32 + ul;        // global unit

    float cst[2] = {0.f, 0.f};               // rows g, g+8
    float zq[4][2];                          // [gate][row half]

    // prefetch zx for t=0
#pragma unroll
    for (int half = 0; half < 2; half++) {
        long row = (long)(b0 + half * 8 + g) * T_ + 0;
#pragma unroll
        for (int gt = 0; gt < 4; gt++)
            zq[gt][half] = zx[row * G_ + gt * U_ + uglob];
    }

    for (int t = 0; t < T_; t++) {
        float acc[2][4];                     // [nf][quad]
#pragma unroll
        for (int nf = 0; nf < 2; nf++)
#pragma unroll
            for (int q = 0; q < 4; q++) acc[nf][q] = 0.f;

        if (t > 0) {
            // wait for all slots of step t-1, pull via DSMEM into swizzled panels
            asm volatile("barrier.cluster.wait.aligned;" ::: "memory");
            const uint32_t buf = (uint32_t)((t - 1) & 1) * 2048u;
#pragma unroll
            for (int j = 0; j < 2; j++) {
                int idx = tid + j * 256;         // 0..511
                int r = idx >> 5, kq = idx & 31;
                int k = kq * 8;
                uint32_t rank = (uint32_t)(kq >> 2);
                uint32_t soff = buf + (uint32_t)(r * 64 + (k & 31) * 2);
                uint32_t la_hi = sbase + SM_SLOT + soff;
                uint32_t ra_hi = mapa_cluster(la_hi, rank);
                uint32_t h0, h1, h2, h3, l0, l1, l2, l3;
                ld_dsmem4(ra_hi, h0, h1, h2, h3);
                ld_dsmem4(ra_hi + 1024u, l0, l1, l2, l3);
                int p = k >> 6, ko = k & 63;
                uint32_t dst = sw128((uint32_t)(r * 128 + ko * 2));
                *(uint4*)(smem + SM_H_HI + p * 2048 + dst) = make_uint4(h0, h1, h2, h3);
                *(uint4*)(smem + SM_H_LO + p * 2048 + dst) = make_uint4(l0, l1, l2, l3);
            }
            __syncthreads();

            // 16 k-chunks: A x4 pair + B x4 pair + 6 HMMA each
#pragma unroll
            for (int kc = 0; kc < 16; kc++) {
                const int p = kc >> 2;
                const int kb = (kc & 3) * 16;
                int mrow = (lane & 7) + ((lane >> 3) & 1) * 8;
                int koffA = kb + (lane >> 4) * 8;
                uint32_t soA = (uint32_t)(p * 2048) + sw128((uint32_t)(mrow * 128 + koffA * 2));
                uint32_t ah[4], al[4];
                ldsm_x4(sbase + SM_H_HI + soA, ah[0], ah[1], ah[2], ah[3]);
                ldsm_x4(sbase + SM_H_LO + soA, al[0], al[1], al[2], al[3]);
                int nrow = warp_n * 16 + (lane & 7) + (lane >> 4) * 8;
                int koffB = kb + ((lane >> 3) & 1) * 8;
                uint32_t soB = (uint32_t)(p * 16384) + sw128((uint32_t)(nrow * 128 + koffB * 2));
                uint32_t bh[4], bl[4];
                ldsm_x4(sbase + SM_U_HI + soB, bh[0], bh[1], bh[2], bh[3]);
                ldsm_x4(sbase + SM_U_LO + soB, bl[0], bl[1], bl[2], bl[3]);
#pragma unroll
                for (int nf = 0; nf < 2; nf++) {
                    mma_bf16(acc[nf], ah, bh[nf * 2], bh[nf * 2 + 1]);
                    mma_bf16(acc[nf], ah, bl[nf * 2], bl[nf * 2 + 1]);
                    mma_bf16(acc[nf], al, bh[nf * 2], bh[nf * 2 + 1]);
                }
            }
        }

        // gates + state update + h stores (slot + global)
        // thread cols: nf=0 -> (gate i, gate f), nf=1 -> (gate g, gate o) of unit uglob
        const uint32_t wbuf = (uint32_t)(t & 1) * 2048u;
#pragma unroll
        for (int half = 0; half < 2; half++) {
            long row = (long)(b0 + half * 8 + g) * T_ + t;
            float ig = 1.f / (1.f + expf(-(zq[0][half] + acc[0][half * 2 + 0])));
            float fg = 1.f / (1.f + expf(-(zq[1][half] + acc[0][half * 2 + 1])));
            float gg = fmaxf(zq[2][half] + acc[1][half * 2 + 0], 0.f);
            float og = 1.f / (1.f + expf(-(zq[3][half] + acc[1][half * 2 + 1])));
            float c  = fg * cst[half] + ig * gg;
            cst[half] = c;
            float h = og * fmaxf(c, 0.f);
            __nv_bfloat16 phi, plo;
            bf16split(h, phi, plo);
            int rloc = half * 8 + g;
            *(uint16_t*)(smem + SM_SLOT + wbuf + rloc * 64 + ul * 2) = *(uint16_t*)&phi;
            *(uint16_t*)(smem + SM_SLOT + wbuf + 1024 + rloc * 64 + ul * 2) = *(uint16_t*)&plo;
            hhi[row * U_ + uglob] = phi;
            hlo[row * U_ + uglob] = plo;
        }

        if (t < T_ - 1) {
            asm volatile("barrier.cluster.arrive.aligned;" ::: "memory");
            // prefetch zx for t+1 (overlaps with peers catching up)
#pragma unroll
            for (int half = 0; half < 2; half++) {
                long row = (long)(b0 + half * 8 + g) * T_ + (t + 1);
#pragma unroll
                for (int gt = 0; gt < 4; gt++)
                    zq[gt][half] = zx[row * G_ + gt * U_ + uglob];
            }
        }
    }

    // final cluster sync: no CTA may exit while peers could still read its smem
    asm volatile("barrier.cluster.arrive.aligned;" ::: "memory");
    asm volatile("barrier.cluster.wait.aligned;" ::: "memory");
}

// ---------------- host launcher ----------------
extern "C" void kernel_launch(void* const* d_in, const int* in_sizes, int n_in,
                              void* d_out, int out_size) {
    const float* x  = (const float*)d_in[0];
    const float* W0 = (const float*)d_in[1];
    const float* U0 = (const float*)d_in[2];
    const float* b0 = (const float*)d_in[3];
    const float* W1 = (const float*)d_in[4];
    const float* U1 = (const float*)d_in[5];
    const float* b1 = (const float*)d_in[6];
    const float* Wd = (const float*)d_in[7];
    const float* bd = (const float*)d_in[8];
    float* out = (float*)d_out;

    __nv_bfloat16 *ahi, *alo, *bhi, *blo, *uhi, *ulo, *hhi, *hlo;
    float *zx_p;
    cudaGetSymbolAddress((void**)&ahi, g_ahi);
    cudaGetSymbolAddress((void**)&alo, g_alo);
    cudaGetSymbolAddress((void**)&bhi, g_bhi);
    cudaGetSymbolAddress((void**)&blo, g_blo);
    cudaGetSymbolAddress((void**)&uhi, g_uhi);
    cudaGetSymbolAddress((void**)&ulo, g_ulo);
    cudaGetSymbolAddress((void**)&hhi, g_hhi);
    cudaGetSymbolAddress((void**)&hlo, g_hlo);
    cudaGetSymbolAddress((void**)&zx_p, g_zx);

    cudaFuncSetAttribute(lstm_kernel, cudaFuncAttributeMaxDynamicSharedMemorySize, LSTM_SMEM);
    cudaFuncSetAttribute(mma_gemm_kernel<false>, cudaFuncAttributeMaxDynamicSharedMemorySize, MM_SMEM);
    cudaFuncSetAttribute(mma_gemm_kernel<true>,  cudaFuncAttributeMaxDynamicSharedMemorySize, MM_SMEM);

    // x -> (B*T, 960) bf16 hi/lo (coalesced tiled transpose)
    transpose_x_kernel<<<dim3(10, B_), 256>>>(x);

    // W0 -> (1024, 960) K-major hi/lo ; U0 -> permuted
    {
        long total = (long)G_ * K0P;
        wtrans_kernel<<<(int)((total + 255) / 256), 256>>>(W0, K0, G_, K0P);
        long tu = (long)G_ * U_;
        utrans_kernel<<<(int)((tu + 255) / 256), 256>>>(U0);
    }
    // zx = x @ W0 + b0
    mma_gemm_kernel<false><<<dim3(G_ / 128, M_ / 128), 256, MM_SMEM>>>(
        ahi, alo, bhi, blo, b0, zx_p, K0P, G_);

    // LSTM layer 0 -> hhi/hlo
    lstm_kernel<<<128, 256, LSTM_SMEM>>>(zx_p, uhi, ulo, hhi, hlo);

    // W1 -> (1024, 256) K-major hi/lo ; U1 -> permuted
    {
        long total = (long)G_ * U_;
        wtrans_kernel<<<(int)((total + 255) / 256), 256>>>(W1, U_, G_, U_);
        utrans_kernel<<<(int)((total + 255) / 256), 256>>>(U1);
    }
    // zx = h0 @ W1 + b1
    mma_gemm_kernel<false><<<dim3(G_ / 128, M_ / 128), 256, MM_SMEM>>>(
        hhi, hlo, bhi, blo, b1, zx_p, U_, G_);

    // LSTM layer 1 -> hhi/hlo
    lstm_kernel<<<128, 256, LSTM_SMEM>>>(zx_p, uhi, ulo, hhi, hlo);

    // Wd -> (600, 256) K-major hi/lo
    {
        long total = (long)ND * U_;
        wtrans_kernel<<<(int)((total + 255) / 256), 256>>>(Wd, U_, ND, U_);
    }
    // out = h1 @ Wd + bd, scattered to (B, N, T, 2)
    mma_gemm_kernel<true><<<dim3((ND + 127) / 128, M_ / 128), 256, MM_SMEM>>>(
        hhi, hlo, bhi, blo, bd, out, U_, ND);
}

// round 11
// speedup vs baseline: 1.3567x; 1.3567x over previous
#include <cuda_runtime.h>
#include <cuda_bf16.h>
#include <math.h>
#include <stdint.h>

#define B_   256
#define N_   300
#define T_   64
#define FIN  3
#define U_   256
#define G_   1024            // 4*U_
#define K0   900             // N_*FIN
#define K0P  960             // padded to multiple of 64
#define M_   16384           // B_*T_
#define FOUT 2
#define ND   600             // N_*FOUT

// ---------------- scratch (static device globals; no allocation) ----------------
__device__ __nv_bfloat16 g_ahi[(size_t)M_ * K0P];   // x transposed, bf16-hi
__device__ __nv_bfloat16 g_alo[(size_t)M_ * K0P];   // x transposed, bf16-lo
__device__ __nv_bfloat16 g_bhi[(size_t)G_ * K0P];   // weight K-major, bf16-hi (max size)
__device__ __nv_bfloat16 g_blo[(size_t)G_ * K0P];
__device__ __nv_bfloat16 g_uhi[(size_t)G_ * U_];    // recurrent U, permuted K-major, hi
__device__ __nv_bfloat16 g_ulo[(size_t)G_ * U_];
__device__ __nv_bfloat16 g_hhi[(size_t)M_ * U_];    // h sequence bf16-hi
__device__ __nv_bfloat16 g_hlo[(size_t)M_ * U_];    // h sequence bf16-lo
__device__ float    g_zx[(size_t)M_ * G_];          // gate pre-acts
__device__ unsigned g_bar[2][16];                   // per-(layer, batch-tile) counters

__global__ void reset_bar_kernel() {
    int i = threadIdx.x;
    if (i < 16) { g_bar[0][i] = 0u; g_bar[1][i] = 0u; }
}

// single dynamic-smem symbol for all kernels
extern __shared__ char dynsmem[];

// ---------------- bf16 2-term split ----------------
__device__ __forceinline__ void bf16split(float v, __nv_bfloat16& hi, __nv_bfloat16& lo) {
    hi = __float2bfloat16(v);
    lo = __float2bfloat16(v - __bfloat162float(hi));
}

// ---------------- coalesced input transpose + split ----------------
// x (B,N,T,F) -> (B*T, 960) bf16 hi/lo, via smem tile (32 n-rows x 192 floats).
__global__ void transpose_x_kernel(const float* __restrict__ x) {
    __shared__ float tile[32][195];          // pitch 195 to spread banks
    const int tid = threadIdx.x;
    const int b = blockIdx.y;
    const int n0 = blockIdx.x * 32;
    const float* xb = x + (size_t)b * N_ * T_ * FIN + (size_t)n0 * T_ * FIN;

    // coalesced read: each n-row is 192 contiguous floats
    for (int idx = tid; idx < 32 * 192; idx += 256) {
        int nl = idx / 192, j = idx - nl * 192;
        float v = (n0 + nl < N_) ? xb[nl * 192 + j] : 0.f;
        tile[nl][j] = v;
    }
    __syncthreads();

    // coalesced write: per output row t, 96 contiguous cols (bf16)
    long rowbase = (long)b * T_;
    for (int idx = tid; idx < 64 * 96; idx += 256) {
        int t = idx / 96, cl = idx - t * 96;
        int nl = cl / 3, f = cl - nl * 3;
        float v = tile[nl][t * 3 + f];
        __nv_bfloat16 hi, lo;
        bf16split(v, hi, lo);
        long o = (rowbase + t) * K0P + n0 * 3 + cl;
        g_ahi[o] = hi;
        g_alo[o] = lo;
    }
}

// ---------------- weight transpose + split: W (K,N) -> (N, Ks) K-major hi/lo ----------------
__global__ void wtrans_kernel(const float* __restrict__ W, int K, int N, int Ks) {
    long i = (long)blockIdx.x * blockDim.x + threadIdx.x;
    if (i >= (long)N * Ks) return;
    int k = (int)(i % Ks);
    int n = (int)(i / Ks);
    float v = (k < K) ? W[(long)k * N + n] : 0.f;
    __nv_bfloat16 hi, lo;
    bf16split(v, hi, lo);
    g_bhi[i] = hi;
    g_blo[i] = lo;
}

// ---------------- recurrent-U permute + split ----------------
// permuted col cp -> (gate, unit): ublk=cp>>7, local=cp&127, warp_n=local>>4, c=local&15,
// gate=(c>>3)*2+(c&1), unit=ublk*32+warp_n*4+((c>>1)&3); orig col = gate*256+unit.
__global__ void utrans_kernel(const float* __restrict__ U) {
    long i = (long)blockIdx.x * blockDim.x + threadIdx.x;
    if (i >= (long)G_ * U_) return;
    int k  = (int)(i & 255);
    int cp = (int)(i >> 8);
    int ublk = cp >> 7;
    int local = cp & 127;
    int warp_n = local >> 4;
    int c = local & 15;
    int gate = ((c >> 3) << 1) | (c & 1);
    int unit = ublk * 32 + warp_n * 4 + ((c >> 1) & 3);
    float v = U[(long)k * G_ + gate * U_ + unit];
    __nv_bfloat16 hi, lo;
    bf16split(v, hi, lo);
    g_uhi[i] = hi;
    g_ulo[i] = lo;
}

// ================= mma.sync helpers =================
__device__ __forceinline__ uint32_t smem_u32(const void* p) {
    uint32_t a;
    asm("{ .reg .u64 t; cvta.to.shared.u64 t, %1; cvt.u32.u64 %0, t; }" : "=r"(a) : "l"(p));
    return a;
}
__device__ __forceinline__ uint32_t sw128(uint32_t o) { return o ^ ((o >> 3) & 0x70); }

__device__ __forceinline__ void ldsm_x4(uint32_t addr, uint32_t& r0, uint32_t& r1,
                                        uint32_t& r2, uint32_t& r3) {
    asm volatile("ldmatrix.sync.aligned.m8n8.x4.shared.b16 {%0,%1,%2,%3}, [%4];"
                 : "=r"(r0), "=r"(r1), "=r"(r2), "=r"(r3) : "r"(addr));
}

__device__ __forceinline__ void mma_bf16(float* d, const uint32_t* a, uint32_t b0, uint32_t b1) {
    asm volatile(
        "mma.sync.aligned.m16n8k16.row.col.f32.bf16.bf16.f32 "
        "{%0,%1,%2,%3}, {%4,%5,%6,%7}, {%8,%9}, {%0,%1,%2,%3};"
        : "+f"(d[0]), "+f"(d[1]), "+f"(d[2]), "+f"(d[3])
        : "r"(a[0]), "r"(a[1]), "r"(a[2]), "r"(a[3]), "r"(b0), "r"(b1));
}

__device__ __forceinline__ void cp_async16(uint32_t dst, const void* src, uint32_t src_bytes) {
    asm volatile("cp.async.cg.shared.global [%0], [%1], 16, %2;"
                 :: "r"(dst), "l"(src), "r"(src_bytes));
}

// ---------------- tensor-core GEMM (feed-forward): C = A @ B^T + bias ----------------
// 128x128 tile, BK=64, 256 threads, double-buffered cp.async (2 x 64KB stages).
#define ST_A_HI 0
#define ST_A_LO 16384
#define ST_B_HI 32768
#define ST_B_LO 49152
#define STAGE_SZ 65536
#define MM_SMEM  131072

template <bool SCATTER>
__global__ void __launch_bounds__(256, 1)
mma_gemm_kernel(const __nv_bfloat16* __restrict__ Ahi, const __nv_bfloat16* __restrict__ Alo,
                const __nv_bfloat16* __restrict__ Bhi, const __nv_bfloat16* __restrict__ Blo,
                const float* __restrict__ bias, float* __restrict__ C,
                int Ks, int N) {
    char* smem = dynsmem;
    const int tid  = threadIdx.x;
    const int lane = tid & 31;
    const int wid  = tid >> 5;
    const int warp_m = wid >> 2;       // 0..1 -> 64 rows
    const int warp_n = wid & 3;        // 0..3 -> 32 cols
    const int m0 = blockIdx.y * 128;
    const int n0 = blockIdx.x * 128;
    const uint32_t sbase = smem_u32(smem);

    float acc[4][4][4];
#pragma unroll
    for (int i = 0; i < 4; i++)
#pragma unroll
        for (int j = 0; j < 4; j++)
#pragma unroll
            for (int q = 0; q < 4; q++) acc[i][j][q] = 0.f;

    const int iters = Ks >> 6;

    auto load_stage = [&](int kt, int buf) {
        uint32_t bb = sbase + (uint32_t)buf * STAGE_SZ;
#pragma unroll
        for (int i = 0; i < 4; i++) {
            int idx = tid + i * 256;            // 0..1023
            int r = idx >> 3, kq = idx & 7;
            uint32_t so = sw128((uint32_t)(r * 128 + kq * 16));
            cp_async16(bb + ST_A_HI + so, Ahi + (size_t)(m0 + r) * Ks + kt + kq * 8, 16u);
            cp_async16(bb + ST_A_LO + so, Alo + (size_t)(m0 + r) * Ks + kt + kq * 8, 16u);
            uint32_t vbytes = (n0 + r < N) ? 16u : 0u;
            int rcl = (n0 + r < N) ? (n0 + r) : 0;
            cp_async16(bb + ST_B_HI + so, Bhi + (size_t)rcl * Ks + kt + kq * 8, vbytes);
            cp_async16(bb + ST_B_LO + so, Blo + (size_t)rcl * Ks + kt + kq * 8, vbytes);
        }
        asm volatile("cp.async.commit_group;" ::: "memory");
    };

    load_stage(0, 0);

    for (int it = 0; it < iters; it++) {
        if (it + 1 < iters) {
            load_stage((it + 1) << 6, (it + 1) & 1);
            asm volatile("cp.async.wait_group 1;" ::: "memory");
        } else {
            asm volatile("cp.async.wait_group 0;" ::: "memory");
        }
        __syncthreads();

        uint32_t bb = sbase + (uint32_t)(it & 1) * STAGE_SZ;
#pragma unroll
        for (int ks = 0; ks < 4; ks++) {
            const int kb = ks * 16;
            uint32_t bh[2][4], bl[2][4];
#pragma unroll
            for (int ng = 0; ng < 2; ng++) {
                int nrow = warp_n * 32 + ng * 16 + (lane & 7) + (lane >> 4) * 8;
                int koff = kb + ((lane >> 3) & 1) * 8;
                uint32_t so = sw128((uint32_t)(nrow * 128 + koff * 2));
                ldsm_x4(bb + ST_B_HI + so, bh[ng][0], bh[ng][1], bh[ng][2], bh[ng][3]);
                ldsm_x4(bb + ST_B_LO + so, bl[ng][0], bl[ng][1], bl[ng][2], bl[ng][3]);
            }
#pragma unroll
            for (int mf = 0; mf < 4; mf++) {
                int mrow = warp_m * 64 + mf * 16 + (lane & 7) + ((lane >> 3) & 1) * 8;
                int koff = kb + (lane >> 4) * 8;
                uint32_t so = sw128((uint32_t)(mrow * 128 + koff * 2));
                uint32_t ah[4], al[4];
                ldsm_x4(bb + ST_A_HI + so, ah[0], ah[1], ah[2], ah[3]);
                ldsm_x4(bb + ST_A_LO + so, al[0], al[1], al[2], al[3]);
#pragma unroll
                for (int ng = 0; ng < 2; ng++) {
#pragma unroll
                    for (int h = 0; h < 2; h++) {
                        int nf = ng * 2 + h;
                        mma_bf16(acc[mf][nf], ah, bh[ng][h * 2], bh[ng][h * 2 + 1]);
                        mma_bf16(acc[mf][nf], ah, bl[ng][h * 2], bl[ng][h * 2 + 1]);
                        mma_bf16(acc[mf][nf], al, bh[ng][h * 2], bh[ng][h * 2 + 1]);
                    }
                }
            }
        }
        __syncthreads();
    }

    const int g  = lane >> 2;
    const int tq = lane & 3;
#pragma unroll
    for (int mf = 0; mf < 4; mf++) {
#pragma unroll
        for (int nf = 0; nf < 4; nf++) {
            int c = n0 + warp_n * 32 + nf * 8 + tq * 2;
            if (c >= N) continue;
            float bx = bias[c], by = bias[c + 1];
#pragma unroll
            for (int half = 0; half < 2; half++) {
                int m = m0 + warp_m * 64 + mf * 16 + g + half * 8;
                float vx = acc[mf][nf][half * 2 + 0] + bx;
                float vy = acc[mf][nf][half * 2 + 1] + by;
                if (SCATTER) {
                    int b = m >> 6, t = m & 63;
                    int nn = c >> 1;
                    float2* p = (float2*)&C[(((long)b * N_ + nn) * T_ + t) * FOUT];
                    *p = make_float2(vx, vy);
                } else {
                    *(float2*)&C[(size_t)m * N + c] = make_float2(vx, vy);
                }
            }
        }
    }
}

// ---------------- tensor-core persistent LSTM layer kernel (N-split, 8 warps) ------------
// 128 blocks = 16 batch-tiles (M=16) x 8 unit-tiles (128 permuted gate-cols).
// 256 threads = 8 warps, each warp owns 16 permuted cols (4 units x 4 gates):
// 96 HMMA/warp/step, no cross-warp reduction. Gates fully thread-local.
// Barrier: scoped per batch-tile, red.release + ld.acquire (no membar.gpu).
#define SM_U_HI  0                    // 4 panels x 16KB
#define SM_U_LO  65536
#define SM_H_HI  131072               // 4 panels x 2KB
#define SM_H_LO  139264
#define LSTM_SMEM 147456

__global__ void __launch_bounds__(256, 1)
lstm_kernel(const float* __restrict__ zx,   // (M_,1024) rows b*T+t, cols gate*256+unit
            const __nv_bfloat16* __restrict__ Uphi,  // permuted (1024,256) K-major
            const __nv_bfloat16* __restrict__ Uplo,
            __nv_bfloat16* __restrict__ hhi,         // (M_,256) rows b*T+t
            __nv_bfloat16* __restrict__ hlo,
            int bar_idx) {
    char* smem = dynsmem;
    const uint32_t sbase = smem_u32(smem);
    const int tid  = threadIdx.x;
    const int lane = tid & 31;
    const int warp_n = tid >> 5;            // 0..7, 16 permuted cols each
    const int ublk = blockIdx.x & 7;
    const int bblk = blockIdx.x >> 3;
    const int b0 = bblk * 16;
    const int cbase = ublk * 128;           // permuted col base

    // ---- load U slice into smem panels (once): 128 rows x 256 k, hi+lo ----
    for (int idx = tid; idx < 4096; idx += 256) {
        int n = idx >> 5, kq = idx & 31;
        int k = kq * 8;
        int p = k >> 6, ko = k & 63;
        uint32_t dst = (uint32_t)(p * 16384) + sw128((uint32_t)(n * 128 + ko * 2));
        *(uint4*)(smem + SM_U_HI + dst) = *(const uint4*)(Uphi + (size_t)(cbase + n) * U_ + k);
        *(uint4*)(smem + SM_U_LO + dst) = *(const uint4*)(Uplo + (size_t)(cbase + n) * U_ + k);
    }
    __syncthreads();

    const int g  = lane >> 2;               // row group 0..7
    const int tq = lane & 3;
    const int uglob = ublk * 32 + warp_n * 4 + tq;   // this thread's unit

    unsigned* bar = &g_bar[bar_idx][bblk];

    float cst[2] = {0.f, 0.f};               // rows g, g+8
    float zq[4][2];                          // [gate][row half]

    // prefetch zx for t=0
#pragma unroll
    for (int half = 0; half < 2; half++) {
        long row = (long)(b0 + half * 8 + g) * T_ + 0;
#pragma unroll
        for (int gt = 0; gt < 4; gt++)
            zq[gt][half] = zx[row * G_ + gt * U_ + uglob];
    }

    for (int t = 0; t < T_; t++) {
        float acc[2][4];                     // [nf][quad]
#pragma unroll
        for (int nf = 0; nf < 2; nf++)
#pragma unroll
            for (int q = 0; q < 4; q++) acc[nf][q] = 0.f;

        if (t > 0) {
            // stage h_{t-1} tile: 16 rows x 256 k, hi+lo
#pragma unroll
            for (int j = 0; j < 2; j++) {
                int idx = tid + j * 256;         // 0..511
                int r = idx >> 5, kq = idx & 31;
                int k = kq * 8;
                int p = k >> 6, ko = k & 63;
                long src = ((long)(b0 + r) * T_ + (t - 1)) * U_ + k;
                uint32_t dst = (uint32_t)(p * 2048) + sw128((uint32_t)(r * 128 + ko * 2));
                *(uint4*)(smem + SM_H_HI + dst) = *(const uint4*)(hhi + src);
                *(uint4*)(smem + SM_H_LO + dst) = *(const uint4*)(hlo + src);
            }
            __syncthreads();

            // 16 k-chunks: A x4 pair + B x4 pair + 6 HMMA each
#pragma unroll
            for (int kc = 0; kc < 16; kc++) {
                const int p = kc >> 2;
                const int kb = (kc & 3) * 16;
                int mrow = (lane & 7) + ((lane >> 3) & 1) * 8;
                int koffA = kb + (lane >> 4) * 8;
                uint32_t soA = (uint32_t)(p * 2048) + sw128((uint32_t)(mrow * 128 + koffA * 2));
                uint32_t ah[4], al[4];
                ldsm_x4(sbase + SM_H_HI + soA, ah[0], ah[1], ah[2], ah[3]);
                ldsm_x4(sbase + SM_H_LO + soA, al[0], al[1], al[2], al[3]);
                int nrow = warp_n * 16 + (lane & 7) + (lane >> 4) * 8;
                int koffB = kb + ((lane >> 3) & 1) * 8;
                uint32_t soB = (uint32_t)(p * 16384) + sw128((uint32_t)(nrow * 128 + koffB * 2));
                uint32_t bh[4], bl[4];
                ldsm_x4(sbase + SM_U_HI + soB, bh[0], bh[1], bh[2], bh[3]);
                ldsm_x4(sbase + SM_U_LO + soB, bl[0], bl[1], bl[2], bl[3]);
#pragma unroll
                for (int nf = 0; nf < 2; nf++) {
                    mma_bf16(acc[nf], ah, bh[nf * 2], bh[nf * 2 + 1]);
                    mma_bf16(acc[nf], ah, bl[nf * 2], bl[nf * 2 + 1]);
                    mma_bf16(acc[nf], al, bh[nf * 2], bh[nf * 2 + 1]);
                }
            }
        }

        // gates + state update + bf16 h store
        // thread cols: nf=0 -> (gate i, gate f), nf=1 -> (gate g, gate o) of unit uglob
#pragma unroll
        for (int half = 0; half < 2; half++) {
            long row = (long)(b0 + half * 8 + g) * T_ + t;
            float ig = 1.f / (1.f + expf(-(zq[0][half] + acc[0][half * 2 + 0])));
            float fg = 1.f / (1.f + expf(-(zq[1][half] + acc[0][half * 2 + 1])));
            float gg = fmaxf(zq[2][half] + acc[1][half * 2 + 0], 0.f);
            float og = 1.f / (1.f + expf(-(zq[3][half] + acc[1][half * 2 + 1])));
            float c  = fg * cst[half] + ig * gg;
            cst[half] = c;
            float h = og * fmaxf(c, 0.f);
            __nv_bfloat16 phi, plo;
            bf16split(h, phi, plo);
            hhi[row * U_ + uglob] = phi;
            hlo[row * U_ + uglob] = plo;
        }

        if (t < T_ - 1) {
            // prefetch zx for t+1 (overlaps with barrier wait)
#pragma unroll
            for (int half = 0; half < 2; half++) {
                long row = (long)(b0 + half * 8 + g) * T_ + (t + 1);
#pragma unroll
                for (int gt = 0; gt < 4; gt++)
                    zq[gt][half] = zx[row * G_ + gt * U_ + uglob];
            }
            // per-batch-tile barrier: release-add, acquire-poll (no membar.gpu)
            __syncthreads();
            if (tid == 0) {
                asm volatile("red.release.gpu.global.add.u32 [%0], 1;" :: "l"(bar) : "memory");
                unsigned target = 8u * (unsigned)(t + 1);
                unsigned v;
                do {
                    asm volatile("ld.acquire.gpu.global.u32 %0, [%1];" : "=r"(v) : "l"(bar) : "memory");
                } while (v < target);
            }
            __syncthreads();
        }
    }
}

// ---------------- host launcher ----------------
extern "C" void kernel_launch(void* const* d_in, const int* in_sizes, int n_in,
                              void* d_out, int out_size) {
    const float* x  = (const float*)d_in[0];
    const float* W0 = (const float*)d_in[1];
    const float* U0 = (const float*)d_in[2];
    const float* b0 = (const float*)d_in[3];
    const float* W1 = (const float*)d_in[4];
    const float* U1 = (const float*)d_in[5];
    const float* b1 = (const float*)d_in[6];
    const float* Wd = (const float*)d_in[7];
    const float* bd = (const float*)d_in[8];
    float* out = (float*)d_out;

    __nv_bfloat16 *ahi, *alo, *bhi, *blo, *uhi, *ulo, *hhi, *hlo;
    float *zx_p;
    cudaGetSymbolAddress((void**)&ahi, g_ahi);
    cudaGetSymbolAddress((void**)&alo, g_alo);
    cudaGetSymbolAddress((void**)&bhi, g_bhi);
    cudaGetSymbolAddress((void**)&blo, g_blo);
    cudaGetSymbolAddress((void**)&uhi, g_uhi);
    cudaGetSymbolAddress((void**)&ulo, g_ulo);
    cudaGetSymbolAddress((void**)&hhi, g_hhi);
    cudaGetSymbolAddress((void**)&hlo, g_hlo);
    cudaGetSymbolAddress((void**)&zx_p, g_zx);

    cudaFuncSetAttribute(lstm_kernel, cudaFuncAttributeMaxDynamicSharedMemorySize, LSTM_SMEM);
    cudaFuncSetAttribute(mma_gemm_kernel<false>, cudaFuncAttributeMaxDynamicSharedMemorySize, MM_SMEM);
    cudaFuncSetAttribute(mma_gemm_kernel<true>,  cudaFuncAttributeMaxDynamicSharedMemorySize, MM_SMEM);

    reset_bar_kernel<<<1, 32>>>();

    // x -> (B*T, 960) bf16 hi/lo (coalesced tiled transpose)
    transpose_x_kernel<<<dim3(10, B_), 256>>>(x);

    // W0 -> (1024, 960) K-major hi/lo ; U0 -> permuted
    {
        long total = (long)G_ * K0P;
        wtrans_kernel<<<(int)((total + 255) / 256), 256>>>(W0, K0, G_, K0P);
        long tu = (long)G_ * U_;
        utrans_kernel<<<(int)((tu + 255) / 256), 256>>>(U0);
    }
    // zx = x @ W0 + b0
    mma_gemm_kernel<false><<<dim3(G_ / 128, M_ / 128), 256, MM_SMEM>>>(
        ahi, alo, bhi, blo, b0, zx_p, K0P, G_);

    // LSTM layer 0 -> hhi/hlo
    lstm_kernel<<<128, 256, LSTM_SMEM>>>(zx_p, uhi, ulo, hhi, hlo, 0);

    // W1 -> (1024, 256) K-major hi/lo ; U1 -> permuted
    {
        long total = (long)G_ * U_;
        wtrans_kernel<<<(int)((total + 255) / 256), 256>>>(W1, U_, G_, U_);
        utrans_kernel<<<(int)((total + 255) / 256), 256>>>(U1);
    }
    // zx = h0 @ W1 + b1
    mma_gemm_kernel<false><<<dim3(G_ / 128, M_ / 128), 256, MM_SMEM>>>(
        hhi, hlo, bhi, blo, b1, zx_p, U_, G_);

    // LSTM layer 1 -> hhi/hlo
    lstm_kernel<<<128, 256, LSTM_SMEM>>>(zx_p, uhi, ulo, hhi, hlo, 1);

    // Wd -> (600, 256) K-major hi/lo
    {
        long total = (long)ND * U_;
        wtrans_kernel<<<(int)((total + 255) / 256), 256>>>(Wd, U_, ND, U_);
    }
    // out = h1 @ Wd + bd, scattered to (B, N, T, 2)
    mma_gemm_kernel<true><<<dim3((ND + 127) / 128, M_ / 128), 256, MM_SMEM>>>(
        hhi, hlo, bhi, blo, bd, out, U_, ND);
}